// round 13
// baseline (speedup 1.0000x reference)
#include <cuda_runtime.h>
#include <cuda_bf16.h>
#include <cuda_fp16.h>
#include <cstdint>

#define HID 2048
#define INTER 8192
#define RANK 16
#define SEQ 2048
#define NB 4
#define MTOT 8192
#define KSEL 10

#define BM 128
#define BN 128
#define BK 32
#define LDSTRIDE 40
#define TILE_B (128 * LDSTRIDE * 2)        // 10240 B per 128-row operand array
// up GEMM: 4 arrays (Ah,Al,Bh,Bl), 2 stages, 2 CTA/SM
#define UP_STAGE_B (4 * TILE_B)            // 40960
#define UP_SMEM (2 * UP_STAGE_B)           // 81920
// down GEMM: BN=64; arrays A(128r)=10240, Bh(64r)=5120, Bl(64r)=5120
#define DBN 64
#define DN_TILE_BB (64 * LDSTRIDE * 2)     // 5120
#define DN_STAGE_B (TILE_B + 2 * DN_TILE_BB)  // 20480
#define DN_SMEM (3 * DN_STAGE_B)           // 61440

// ---------------- device scratch ----------------
__device__ __half g_x2f[(size_t)MTOT * INTER];
__device__ __nv_bfloat16 g_x1h[(size_t)MTOT * HID];
__device__ __nv_bfloat16 g_x1l[(size_t)MTOT * HID];
__device__ __nv_bfloat16 g_wupT_h[(size_t)INTER * HID];
__device__ __nv_bfloat16 g_wupT_l[(size_t)INTER * HID];
__device__ __half g_wdnT_f[(size_t)HID * INTER];
__device__ __half g_wdnT_ls[(size_t)HID * INTER];
__device__ float g_tup[MTOT * RANK];
__device__ float g_tdn[MTOT * RANK];
__device__ __nv_bfloat16 g_lth[MTOT * 32];
__device__ __nv_bfloat16 g_ltl[MTOT * 32];
__device__ __half g_ltf[MTOT * 32];
__device__ __nv_bfloat16 g_lubh[INTER * 32];
__device__ __nv_bfloat16 g_lubl[INTER * 32];
__device__ __half g_ldbf[HID * 32];
__device__ __half g_ldbls[HID * 32];
__device__ int g_zero[NB * INTER];
__device__ int g_topk[NB * KSEL];

// ---------------- helpers ----------------
__device__ __forceinline__ uint32_t smem_u32(const void* p) {
    uint32_t a;
    asm("{ .reg .u64 t; cvta.to.shared.u64 t, %1; cvt.u32.u64 %0, t; }" : "=r"(a) : "l"(p));
    return a;
}
__device__ __forceinline__ void split1(float x, __nv_bfloat16& h, __nv_bfloat16& l) {
    h = __float2bfloat16(x);
    l = __float2bfloat16(x - __bfloat162float(h));
}
__device__ __forceinline__ void split1f(float x, __half& h, __half& ls) {
    h = __float2half(x);
    ls = __float2half((x - __half2float(h)) * 1024.0f);
}
__device__ __forceinline__ uint32_t packbf(__nv_bfloat16 a, __nv_bfloat16 b) {
    __nv_bfloat162 t = __halves2bfloat162(a, b);
    return *reinterpret_cast<uint32_t*>(&t);
}
__device__ __forceinline__ uint32_t packh(__half a, __half b) {
    __half2 t = __halves2half2(a, b);
    return *reinterpret_cast<uint32_t*>(&t);
}
__device__ __forceinline__ void cpasync16(uint32_t dst, const void* src) {
    asm volatile("cp.async.cg.shared.global [%0], [%1], 16;" :: "r"(dst), "l"(src));
}
__device__ __forceinline__ void ldsm4(uint32_t (&r)[4], uint32_t addr) {
    asm volatile("ldmatrix.sync.aligned.m8n8.x4.shared.b16 {%0,%1,%2,%3}, [%4];"
                 : "=r"(r[0]), "=r"(r[1]), "=r"(r[2]), "=r"(r[3]) : "r"(addr));
}
__device__ __forceinline__ void mma_bf(float (&d)[4], const uint32_t (&a)[4], const uint32_t* b) {
    asm volatile("mma.sync.aligned.m16n8k16.row.col.f32.bf16.bf16.f32 "
                 "{%0,%1,%2,%3},{%4,%5,%6,%7},{%8,%9},{%0,%1,%2,%3};"
                 : "+f"(d[0]), "+f"(d[1]), "+f"(d[2]), "+f"(d[3])
                 : "r"(a[0]), "r"(a[1]), "r"(a[2]), "r"(a[3]), "r"(b[0]), "r"(b[1]));
}
__device__ __forceinline__ void mma_fp(float (&d)[4], const uint32_t (&a)[4], const uint32_t* b) {
    asm volatile("mma.sync.aligned.m16n8k16.row.col.f32.f16.f16.f32 "
                 "{%0,%1,%2,%3},{%4,%5,%6,%7},{%8,%9},{%0,%1,%2,%3};"
                 : "+f"(d[0]), "+f"(d[1]), "+f"(d[2]), "+f"(d[3])
                 : "r"(a[0]), "r"(a[1]), "r"(a[2]), "r"(a[3]), "r"(b[0]), "r"(b[1]));
}
__device__ __forceinline__ void mma_hh(uint32_t (&d)[2], const uint32_t (&a)[4], const uint32_t* b) {
    asm volatile("mma.sync.aligned.m16n8k16.row.col.f16.f16.f16.f16 "
                 "{%0,%1},{%2,%3,%4,%5},{%6,%7},{%0,%1};"
                 : "+r"(d[0]), "+r"(d[1])
                 : "r"(a[0]), "r"(a[1]), "r"(a[2]), "r"(a[3]), "r"(b[0]), "r"(b[1]));
}

// ---------------- launch 1: fused prep ----------------
#define P0 16384                 // x1 split -> bf16 pair
#define P1 (P0 + 16384)          // w_up transpose + bf16 split
#define P2 (P1 + 1024)           // lora_b up (bf16 pair, padded)
#define P3 (P2 + 128)            // zero g_zero
#define P4 (P3 + 16384)          // w_down transpose + f16 split
#define P5 (P4 + 256)            // lora_b down (f16 pair, padded)
#define P6 (P5 + 128)            // zero g_tup
#define PREP_GRID (P6 + 128)     // zero g_tdn
__global__ __launch_bounds__(256) void prep_fused(
    const float* __restrict__ x1, const float* __restrict__ w_up,
    const float* __restrict__ w_up_lb,
    const float* __restrict__ w_down, const float* __restrict__ w_down_lb)
{
    __shared__ float t[32][33];
    const int bid = blockIdx.x, tid = threadIdx.x;
    if (bid < P0) {
        size_t i = (size_t)bid * 256 + tid;
        float4 v = *(const float4*)(x1 + i * 4);
        __nv_bfloat16 h0, h1, h2, h3, l0, l1, l2, l3;
        split1(v.x, h0, l0); split1(v.y, h1, l1);
        split1(v.z, h2, l2); split1(v.w, h3, l3);
        ((uint2*)g_x1h)[i] = make_uint2(packbf(h0, h1), packbf(h2, h3));
        ((uint2*)g_x1l)[i] = make_uint2(packbf(l0, l1), packbf(l2, l3));
    } else if (bid < P1) {
        int tb = bid - P0;
        int bx = tb & 255, by = tb >> 8;
        const int tx = tid & 31, ty = tid >> 5;
        const int r0 = by * 32, c0 = bx * 32;
#pragma unroll
        for (int i = 0; i < 4; i++) {
            int r = ty + i * 8;
            t[r][tx] = w_up[(size_t)(r0 + r) * INTER + c0 + tx];
        }
        __syncthreads();
#pragma unroll
        for (int i = 0; i < 4; i++) {
            int c = ty + i * 8;
            __nv_bfloat16 h, l;
            split1(t[tx][c], h, l);
            g_wupT_h[(size_t)(c0 + c) * HID + r0 + tx] = h;
            g_wupT_l[(size_t)(c0 + c) * HID + r0 + tx] = l;
        }
    } else if (bid < P2) {
        int i = (bid - P1) * 256 + tid;
        int n = i >> 5, j = i & 31;
        float v = (j < 16) ? w_up_lb[(size_t)j * INTER + n] : 0.0f;
        __nv_bfloat16 h, l;
        split1(v, h, l);
        g_lubh[i] = h; g_lubl[i] = l;
    } else if (bid < P3) {
        int i = (bid - P2) * 256 + tid;
        if (i < NB * INTER) g_zero[i] = 0;
    } else if (bid < P4) {
        int tb = bid - P3;
        int bx = tb & 63, by = tb >> 6;
        const int tx = tid & 31, ty = tid >> 5;
        const int r0 = by * 32, c0 = bx * 32;
#pragma unroll
        for (int i = 0; i < 4; i++) {
            int r = ty + i * 8;
            t[r][tx] = w_down[(size_t)(r0 + r) * HID + c0 + tx];
        }
        __syncthreads();
#pragma unroll
        for (int i = 0; i < 4; i++) {
            int c = ty + i * 8;
            __half h, ls;
            split1f(t[tx][c], h, ls);
            g_wdnT_f[(size_t)(c0 + c) * INTER + r0 + tx] = h;
            g_wdnT_ls[(size_t)(c0 + c) * INTER + r0 + tx] = ls;
        }
    } else if (bid < P5) {
        int i = (bid - P4) * 256 + tid;
        int n = i >> 5, j = i & 31;
        float v = (j < 16) ? w_down_lb[(size_t)j * HID + n] : 0.0f;
        __half h, ls;
        split1f(v, h, ls);
        g_ldbf[i] = h; g_ldbls[i] = ls;
    } else if (bid < P6) {
        int i = (bid - P5) * 256 + tid;
        ((float4*)g_tup)[i] = make_float4(0.f, 0.f, 0.f, 0.f);
    } else {
        int i = (bid - P6) * 256 + tid;
        ((float4*)g_tdn)[i] = make_float4(0.f, 0.f, 0.f, 0.f);
    }
}

// ---------------- rank-16 GEMM, K-split ----------------
template <typename TIN>
__global__ __launch_bounds__(256) void rank16_partial(
    const TIN* __restrict__ X, const float* __restrict__ A16,
    float* __restrict__ T, int K, int kchunk)
{
    const int wid = threadIdx.x >> 5, lane = threadIdx.x & 31;
    const int row0 = (blockIdx.x * 8 + wid) * 4;
    const int kbase = blockIdx.y * kchunk;
    float acc[4][16];
#pragma unroll
    for (int r = 0; r < 4; r++)
#pragma unroll
        for (int j = 0; j < 16; j++) acc[r][j] = 0.0f;
    for (int k0 = kbase + lane * 4; k0 < kbase + kchunk; k0 += 128) {
        float xv[4][4];
#pragma unroll
        for (int r = 0; r < 4; r++) {
            if constexpr (sizeof(TIN) == 4) {
                float4 v = *(const float4*)(X + (size_t)(row0 + r) * K + k0);
                xv[r][0] = v.x; xv[r][1] = v.y; xv[r][2] = v.z; xv[r][3] = v.w;
            } else {
                uint2 u = *(const uint2*)(X + (size_t)(row0 + r) * K + k0);
                __half2 p0 = *reinterpret_cast<__half2*>(&u.x);
                __half2 p1 = *reinterpret_cast<__half2*>(&u.y);
                float2 f0 = __half22float2(p0), f1 = __half22float2(p1);
                xv[r][0] = f0.x; xv[r][1] = f0.y; xv[r][2] = f1.x; xv[r][3] = f1.y;
            }
        }
#pragma unroll
        for (int e = 0; e < 4; e++) {
            const float* Ar = A16 + (size_t)(k0 + e) * 16;
            float av[16];
#pragma unroll
            for (int j = 0; j < 16; j += 4) {
                float4 a = *(const float4*)(Ar + j);
                av[j] = a.x; av[j + 1] = a.y; av[j + 2] = a.z; av[j + 3] = a.w;
            }
#pragma unroll
            for (int r = 0; r < 4; r++)
#pragma unroll
                for (int j = 0; j < 16; j++) acc[r][j] = fmaf(xv[r][e], av[j], acc[r][j]);
        }
    }
#pragma unroll
    for (int r = 0; r < 4; r++)
#pragma unroll
        for (int j = 0; j < 16; j++)
#pragma unroll
            for (int o = 16; o > 0; o >>= 1)
                acc[r][j] += __shfl_xor_sync(0xffffffffu, acc[r][j], o);
    if (lane < 4) {
        int r = lane;
#pragma unroll
        for (int j = 0; j < 16; j++)
            atomicAdd(&T[(size_t)(row0 + r) * 16 + j], acc[r][j]);
    }
}

// finalize T -> padded split tensors
template <bool F16OUT>
__global__ void lora_finalize(const float* __restrict__ T) {
    int i = blockIdx.x * blockDim.x + threadIdx.x;
    if (i >= MTOT * 32) return;
    int j = i & 31;
    float v = (j < 16) ? T[(i >> 5) * 16 + j] : 0.0f;
    if (F16OUT) {
        g_ltf[i] = __float2half(v);
    } else {
        __nv_bfloat16 h, l;
        split1(v, h, l);
        g_lth[i] = h; g_ltl[i] = l;
    }
}

// ---------------- up GEMM: bf16 3-term, 128x128, 2-stage, 2 CTA/SM ----------
__global__ __launch_bounds__(256, 2) void mma_gemm_up(
    const __nv_bfloat16* __restrict__ A0, const __nv_bfloat16* __restrict__ A1,
    const __nv_bfloat16* __restrict__ B0, const __nv_bfloat16* __restrict__ B1,
    const __nv_bfloat16* __restrict__ lt0, const __nv_bfloat16* __restrict__ lt1,
    const __nv_bfloat16* __restrict__ lb0, const __nv_bfloat16* __restrict__ lb1,
    int N, int K)
{
    extern __shared__ char smem[];
    const uint32_t sbase = smem_u32(smem);
    const int tid = threadIdx.x, lane = tid & 31, wid = tid >> 5;
    const int wm = wid >> 2, wn = wid & 3;
    const int bm = blockIdx.y * BM, bn = blockIdx.x * BN;
    const int nmain = K / BK, ntot = nmain + 1;

    auto issue = [&](int c) {
        const __nv_bfloat16 *pa0, *pa1, *pb0, *pb1;
        int sa, sb;
        if (c < nmain) {
            size_t ao = (size_t)bm * K + c * BK, bo = (size_t)bn * K + c * BK;
            pa0 = A0 + ao; pa1 = A1 + ao; sa = K;
            pb0 = B0 + bo; pb1 = B1 + bo; sb = K;
        } else {
            pa0 = lt0 + (size_t)bm * 32; pa1 = lt1 + (size_t)bm * 32; sa = 32;
            pb0 = lb0 + (size_t)bn * 32; pb1 = lb1 + (size_t)bn * 32; sb = 32;
        }
        uint32_t stage = sbase + (c & 1) * UP_STAGE_B;
#pragma unroll
        for (int q = 0; q < 8; q++) {
            int qi = tid + q * 256;
            int arr = qi >> 9, idx = qi & 511;
            int r = idx >> 2, cc = idx & 3;
            const __nv_bfloat16* src;
            if (arr == 0)      src = pa0 + (size_t)r * sa + cc * 8;
            else if (arr == 1) src = pa1 + (size_t)r * sa + cc * 8;
            else if (arr == 2) src = pb0 + (size_t)r * sb + cc * 8;
            else               src = pb1 + (size_t)r * sb + cc * 8;
            cpasync16(stage + arr * TILE_B + r * (LDSTRIDE * 2) + cc * 16, src);
        }
        asm volatile("cp.async.commit_group;");
    };

    issue(0);

    float acc[4][4][4];
#pragma unroll
    for (int mf = 0; mf < 4; mf++)
#pragma unroll
        for (int nf = 0; nf < 4; nf++)
#pragma unroll
            for (int q = 0; q < 4; q++) acc[mf][nf][q] = 0.0f;

    for (int c = 0; c < ntot; c++) {
        if (c + 1 < ntot) {
            issue(c + 1);
            asm volatile("cp.async.wait_group 1;" ::: "memory");
        } else {
            asm volatile("cp.async.wait_group 0;" ::: "memory");
        }
        __syncthreads();
        const uint32_t stage = sbase + (c & 1) * UP_STAGE_B;
#pragma unroll
        for (int s = 0; s < 2; s++) {
            uint32_t ah[4][4], al[4][4], bh[4][2], bl[4][2];
#pragma unroll
            for (int mf = 0; mf < 4; mf++) {
                uint32_t ra = stage +
                    ((wm * 64 + mf * 16 + (lane & 15)) * LDSTRIDE +
                     s * 16 + (lane >> 4) * 8) * 2;
                ldsm4(ah[mf], ra);
                ldsm4(al[mf], ra + TILE_B);
            }
#pragma unroll
            for (int nf16 = 0; nf16 < 2; nf16++) {
                uint32_t rb = stage + 2 * TILE_B +
                    ((wn * 32 + nf16 * 16 + (lane & 7) + (((lane >> 4) & 1) << 3)) * LDSTRIDE +
                     s * 16 + ((lane >> 3) & 1) * 8) * 2;
                uint32_t t[4];
                ldsm4(t, rb);
                bh[nf16 * 2][0] = t[0]; bh[nf16 * 2][1] = t[1];
                bh[nf16 * 2 + 1][0] = t[2]; bh[nf16 * 2 + 1][1] = t[3];
                ldsm4(t, rb + TILE_B);
                bl[nf16 * 2][0] = t[0]; bl[nf16 * 2][1] = t[1];
                bl[nf16 * 2 + 1][0] = t[2]; bl[nf16 * 2 + 1][1] = t[3];
            }
#pragma unroll
            for (int mf = 0; mf < 4; mf++)
#pragma unroll
                for (int nf = 0; nf < 4; nf++) {
                    mma_bf(acc[mf][nf], ah[mf], bh[nf]);
                    mma_bf(acc[mf][nf], al[mf], bh[nf]);
                    mma_bf(acc[mf][nf], ah[mf], bl[nf]);
                }
        }
        __syncthreads();
    }

    // epilogue: relu + zero counts + fp16 x2 store
    const int r0 = lane >> 2, c0 = (lane & 3) * 2;
    __shared__ int zc[BN];
    if (tid < BN) zc[tid] = 0;
    __syncthreads();
    int cnt0[4] = {0, 0, 0, 0}, cnt1[4] = {0, 0, 0, 0};
#pragma unroll
    for (int mf = 0; mf < 4; mf++)
#pragma unroll
        for (int nf = 0; nf < 4; nf++) {
            float v0 = fmaxf(acc[mf][nf][0], 0.0f);
            float v1 = fmaxf(acc[mf][nf][1], 0.0f);
            float v2 = fmaxf(acc[mf][nf][2], 0.0f);
            float v3 = fmaxf(acc[mf][nf][3], 0.0f);
            cnt0[nf] += (v0 == 0.0f) + (v2 == 0.0f);
            cnt1[nf] += (v1 == 0.0f) + (v3 == 0.0f);
            int ra = bm + wm * 64 + mf * 16 + r0;
            int col = bn + wn * 32 + nf * 8 + c0;
            size_t pa = (size_t)ra * (N / 2) + (col >> 1);
            size_t pb = (size_t)(ra + 8) * (N / 2) + (col >> 1);
            ((uint32_t*)g_x2f)[pa] = packh(__float2half(v0), __float2half(v1));
            ((uint32_t*)g_x2f)[pb] = packh(__float2half(v2), __float2half(v3));
        }
#pragma unroll
    for (int nf = 0; nf < 4; nf++) {
        atomicAdd(&zc[wn * 32 + nf * 8 + c0], cnt0[nf]);
        atomicAdd(&zc[wn * 32 + nf * 8 + c0 + 1], cnt1[nf]);
    }
    __syncthreads();
    if (tid < BN) {
        int b = bm / SEQ;
        atomicAdd(&g_zero[b * INTER + bn + tid], zc[tid]);
    }
}

// ---------------- down GEMM: fp16 dual-acc, 128x64, 3-stage, 3 CTA/SM -------
// acc1 += A*Bh (fp32 acc); acc2 += A*Bls (fp16 acc); y = acc1 + 2^-10 * acc2
// 8 warps as 4(m) x 2(n): warp tile 32x32.
__global__ __launch_bounds__(256, 3) void mma_gemm_down(
    const __half* __restrict__ A0,
    const __half* __restrict__ B0, const __half* __restrict__ B1,
    const __half* __restrict__ lt0,
    const __half* __restrict__ lb0, const __half* __restrict__ lb1,
    float* __restrict__ C, int N, int K)
{
    extern __shared__ char smem[];
    const uint32_t sbase = smem_u32(smem);
    const int tid = threadIdx.x, lane = tid & 31, wid = tid >> 5;
    const int wm = wid >> 1, wn = wid & 1;
    const int bm = blockIdx.y * BM, bn = blockIdx.x * DBN;
    const int nmain = K / BK, ntot = nmain + 1;

    auto issue = [&](int c) {
        const __half *pa, *pb0, *pb1;
        int sa, sb;
        if (c < nmain) {
            pa = A0 + (size_t)bm * K + c * BK; sa = K;
            pb0 = B0 + (size_t)bn * K + c * BK;
            pb1 = B1 + (size_t)bn * K + c * BK; sb = K;
        } else {
            pa = lt0 + (size_t)bm * 32; sa = 32;
            pb0 = lb0 + (size_t)bn * 32; pb1 = lb1 + (size_t)bn * 32; sb = 32;
        }
        uint32_t stage = sbase + (c % 3) * DN_STAGE_B;
#pragma unroll
        for (int q = 0; q < 4; q++) {
            int qi = tid + q * 256;                  // 0..1023
            const __half* src;
            uint32_t dst;
            if (qi < 512) {                          // A: 128 rows x 4 x uint4
                int r = qi >> 2, cc = qi & 3;
                src = pa + (size_t)r * sa + cc * 8;
                dst = stage + r * (LDSTRIDE * 2) + cc * 16;
            } else {                                 // Bh/Bl: 64 rows x 4 each
                int t2 = qi - 512;
                int arr = t2 >> 8, idx = t2 & 255;
                int r = idx >> 2, cc = idx & 3;
                src = (arr ? pb1 : pb0) + (size_t)r * sb + cc * 8;
                dst = stage + TILE_B + arr * DN_TILE_BB + r * (LDSTRIDE * 2) + cc * 16;
            }
            cpasync16(dst, src);
        }
        asm volatile("cp.async.commit_group;");
    };

    issue(0);
    issue(1);

    float acc1[2][4][4];
    uint32_t acc2[2][4][2];
#pragma unroll
    for (int mf = 0; mf < 2; mf++)
#pragma unroll
        for (int nf = 0; nf < 4; nf++) {
#pragma unroll
            for (int q = 0; q < 4; q++) acc1[mf][nf][q] = 0.0f;
            acc2[mf][nf][0] = 0u; acc2[mf][nf][1] = 0u;
        }

    for (int c = 0; c < ntot; c++) {
        if (c + 1 < ntot) {
            asm volatile("cp.async.wait_group 1;" ::: "memory");
        } else {
            asm volatile("cp.async.wait_group 0;" ::: "memory");
        }
        __syncthreads();
        if (c + 2 < ntot) issue(c + 2);
        const uint32_t stage = sbase + (c % 3) * DN_STAGE_B;
#pragma unroll
        for (int s = 0; s < 2; s++) {
            uint32_t ah[2][4], bh[4][2], bl[4][2];
#pragma unroll
            for (int mf = 0; mf < 2; mf++) {
                uint32_t ra = stage +
                    ((wm * 32 + mf * 16 + (lane & 15)) * LDSTRIDE +
                     s * 16 + (lane >> 4) * 8) * 2;
                ldsm4(ah[mf], ra);
            }
#pragma unroll
            for (int nf16 = 0; nf16 < 2; nf16++) {
                uint32_t rb = stage + TILE_B +
                    ((wn * 32 + nf16 * 16 + (lane & 7) + (((lane >> 4) & 1) << 3)) * LDSTRIDE +
                     s * 16 + ((lane >> 3) & 1) * 8) * 2;
                uint32_t t[4];
                ldsm4(t, rb);
                bh[nf16 * 2][0] = t[0]; bh[nf16 * 2][1] = t[1];
                bh[nf16 * 2 + 1][0] = t[2]; bh[nf16 * 2 + 1][1] = t[3];
                ldsm4(t, rb + DN_TILE_BB);
                bl[nf16 * 2][0] = t[0]; bl[nf16 * 2][1] = t[1];
                bl[nf16 * 2 + 1][0] = t[2]; bl[nf16 * 2 + 1][1] = t[3];
            }
#pragma unroll
            for (int mf = 0; mf < 2; mf++)
#pragma unroll
                for (int nf = 0; nf < 4; nf++) {
                    mma_fp(acc1[mf][nf], ah[mf], bh[nf]);
                    mma_hh(acc2[mf][nf], ah[mf], bl[nf]);
                }
        }
    }

    const int r0 = lane >> 2, c0 = (lane & 3) * 2;
    const float sc = 0.0009765625f;   // 2^-10
#pragma unroll
    for (int mf = 0; mf < 2; mf++)
#pragma unroll
        for (int nf = 0; nf < 4; nf++) {
            float2 f0 = __half22float2(*reinterpret_cast<__half2*>(&acc2[mf][nf][0]));
            float2 f1 = __half22float2(*reinterpret_cast<__half2*>(&acc2[mf][nf][1]));
            int ra = bm + wm * 32 + mf * 16 + r0;
            int col = bn + wn * 32 + nf * 8 + c0;
            *(float2*)&C[(size_t)ra * N + col] =
                make_float2(acc1[mf][nf][0] + sc * f0.x, acc1[mf][nf][1] + sc * f0.y);
            *(float2*)&C[(size_t)(ra + 8) * N + col] =
                make_float2(acc1[mf][nf][2] + sc * f1.x, acc1[mf][nf][3] + sc * f1.y);
        }
}

// ---------------- topk + gather ----------------
__global__ void topk_kernel() {
    const int b = blockIdx.x, tid = threadIdx.x;
    __shared__ unsigned red[256];
    __shared__ int chosen[KSEL];
    for (int sel = 0; sel < KSEL; sel++) {
        unsigned best = 0xFFFFFFFFu;
        for (int j = tid; j < INTER; j += 256) {
            bool skip = false;
            for (int c = 0; c < sel; c++) if (chosen[c] == j) skip = true;
            if (!skip) best = min(best, ((unsigned)g_zero[b * INTER + j] << 13) | (unsigned)j);
        }
        red[tid] = best;
        __syncthreads();
        for (int s = 128; s > 0; s >>= 1) {
            if (tid < s) red[tid] = min(red[tid], red[tid + s]);
            __syncthreads();
        }
        if (tid == 0) { chosen[sel] = (int)(red[0] & 8191u); g_topk[b * KSEL + sel] = chosen[sel]; }
        __syncthreads();
    }
}

__global__ void gather_kernel(float* __restrict__ out) {
    int idx = blockIdx.x * blockDim.x + threadIdx.x;
    if (idx >= NB * SEQ * KSEL) return;
    int i = idx % KSEL, row = idx / KSEL, b = row / SEQ;
    out[idx] = __half2float(g_x2f[(size_t)row * INTER + g_topk[b * KSEL + i]]);
}

// ---------------- launch ----------------
extern "C" void kernel_launch(void* const* d_in, const int* in_sizes, int n_in,
                              void* d_out, int out_size)
{
    const float* x1 = (const float*)d_in[0];
    const float* w_up = (const float*)d_in[1];
    const float* w_up_la = (const float*)d_in[2];
    const float* w_up_lb = (const float*)d_in[3];
    const float* w_down = (const float*)d_in[4];
    const float* w_down_la = (const float*)d_in[5];
    const float* w_down_lb = (const float*)d_in[6];
    float* out = (float*)d_out;

    float *ptup, *ptdn;
    __nv_bfloat16 *x1h, *x1l, *uh, *ul, *lth, *ltl, *ubh, *ubl;
    __half *x2f, *wdf, *wdls, *ltf, *dbf, *dbls;
    cudaGetSymbolAddress((void**)&ptup, g_tup);
    cudaGetSymbolAddress((void**)&ptdn, g_tdn);
    cudaGetSymbolAddress((void**)&x1h, g_x1h);
    cudaGetSymbolAddress((void**)&x1l, g_x1l);
    cudaGetSymbolAddress((void**)&uh, g_wupT_h);
    cudaGetSymbolAddress((void**)&ul, g_wupT_l);
    cudaGetSymbolAddress((void**)&lth, g_lth);
    cudaGetSymbolAddress((void**)&ltl, g_ltl);
    cudaGetSymbolAddress((void**)&ubh, g_lubh);
    cudaGetSymbolAddress((void**)&ubl, g_lubl);
    cudaGetSymbolAddress((void**)&x2f, g_x2f);
    cudaGetSymbolAddress((void**)&wdf, g_wdnT_f);
    cudaGetSymbolAddress((void**)&wdls, g_wdnT_ls);
    cudaGetSymbolAddress((void**)&ltf, g_ltf);
    cudaGetSymbolAddress((void**)&dbf, g_ldbf);
    cudaGetSymbolAddress((void**)&dbls, g_ldbls);

    cudaFuncSetAttribute((const void*)mma_gemm_up,
                         cudaFuncAttributeMaxDynamicSharedMemorySize, UP_SMEM);
    cudaFuncSetAttribute((const void*)mma_gemm_down,
                         cudaFuncAttributeMaxDynamicSharedMemorySize, DN_STAGE_B * 3);

    // 1: all elementwise prep
    prep_fused<<<PREP_GRID, 256>>>(x1, w_up, w_up_lb, w_down, w_down_lb);
    // 2: t_up = x1 @ w_up_lora_a  (fp32, exact — counts depend on it)
    rank16_partial<float><<<dim3(MTOT / 32, 4), 256>>>(x1, w_up_la, ptup, HID, HID / 4);
    // 3: finalize lora-T up (bf16 pair)
    lora_finalize<false><<<(MTOT * 32 + 255) / 256, 256>>>(ptup);
    // 4: up GEMM (bf16 3-term — REQUIRED for exact zero counts)
    mma_gemm_up<<<dim3(INTER / BN, MTOT / BM), 256, UP_SMEM>>>(
        x1h, x1l, uh, ul, lth, ltl, ubh, ubl, INTER, HID);
    // 5: t_down = x2f @ w_down_lora_a
    rank16_partial<__half><<<dim3(MTOT / 32, 8), 256>>>(x2f, w_down_la, ptdn, INTER, INTER / 8);
    // 6: finalize lora-T down (fp16)
    lora_finalize<true><<<(MTOT * 32 + 255) / 256, 256>>>(ptdn);
    // 7: down GEMM (fp16 dual-acc, 128x64, 3 CTA/SM)
    mma_gemm_down<<<dim3(HID / DBN, MTOT / BM), 256, DN_SMEM>>>(
        x2f, wdf, wdls, ltf, dbf, dbls, out, HID, INTER);
    // 8/9: topk + gather
    topk_kernel<<<NB, 256>>>();
    gather_kernel<<<(NB * SEQ * KSEL + 255) / 256, 256>>>(out + (size_t)MTOT * HID);
}

// round 14
// speedup vs baseline: 1.6199x; 1.6199x over previous
#include <cuda_runtime.h>
#include <cuda_bf16.h>
#include <cuda_fp16.h>
#include <cstdint>

#define HID 2048
#define INTER 8192
#define RANK 16
#define SEQ 2048
#define NB 4
#define MTOT 8192
#define KSEL 10

#define BM 128
#define BN 128
#define BK 32
// up GEMM: swizzled 64B rows, 4 arrays (Ah,Al,Bh,Bl), 3 stages, 2 CTA/SM
#define UP_TILE 8192                        // 128 rows * 64 B
#define UP_STAGE_B (4 * UP_TILE)            // 32768
#define UP_SMEM (3 * UP_STAGE_B)            // 98304
// down GEMM (round-11 winner): padded stride-40, 3 arrays, 3 stages, 2 CTA/SM
#define LDSTRIDE 40
#define TILE_B (128 * LDSTRIDE * 2)         // 10240
#define DN_STAGE_B (3 * TILE_B)             // 30720
#define DN_SMEM (3 * DN_STAGE_B)            // 92160

// ---------------- device scratch ----------------
__device__ __half g_x2f[(size_t)MTOT * INTER];
__device__ __nv_bfloat16 g_x1h[(size_t)MTOT * HID];
__device__ __nv_bfloat16 g_x1l[(size_t)MTOT * HID];
__device__ __nv_bfloat16 g_wupT_h[(size_t)INTER * HID];
__device__ __nv_bfloat16 g_wupT_l[(size_t)INTER * HID];
__device__ __half g_wdnT_f[(size_t)HID * INTER];
__device__ __half g_wdnT_ls[(size_t)HID * INTER];
__device__ float g_tup[MTOT * RANK];
__device__ float g_tdn[MTOT * RANK];
__device__ __nv_bfloat16 g_lth[MTOT * 32];
__device__ __nv_bfloat16 g_ltl[MTOT * 32];
__device__ __half g_ltf[MTOT * 32];
__device__ __nv_bfloat16 g_lubh[INTER * 32];
__device__ __nv_bfloat16 g_lubl[INTER * 32];
__device__ __half g_ldbf[HID * 32];
__device__ __half g_ldbls[HID * 32];
__device__ int g_zero[NB * INTER];
__device__ int g_topk[NB * KSEL];

// ---------------- helpers ----------------
__device__ __forceinline__ uint32_t smem_u32(const void* p) {
    uint32_t a;
    asm("{ .reg .u64 t; cvta.to.shared.u64 t, %1; cvt.u32.u64 %0, t; }" : "=r"(a) : "l"(p));
    return a;
}
// 64B-row swizzle: 16B chunk c -> c ^ ((row>>1)&3); off = row*64 + c*16
__device__ __forceinline__ uint32_t sw64(uint32_t off) {
    return off ^ (((off >> 7) & 3u) << 4);
}
__device__ __forceinline__ void split1(float x, __nv_bfloat16& h, __nv_bfloat16& l) {
    h = __float2bfloat16(x);
    l = __float2bfloat16(x - __bfloat162float(h));
}
__device__ __forceinline__ void split1f(float x, __half& h, __half& ls) {
    h = __float2half(x);
    ls = __float2half((x - __half2float(h)) * 1024.0f);
}
__device__ __forceinline__ uint32_t packbf(__nv_bfloat16 a, __nv_bfloat16 b) {
    __nv_bfloat162 t = __halves2bfloat162(a, b);
    return *reinterpret_cast<uint32_t*>(&t);
}
__device__ __forceinline__ uint32_t packh(__half a, __half b) {
    __half2 t = __halves2half2(a, b);
    return *reinterpret_cast<uint32_t*>(&t);
}
__device__ __forceinline__ void cpasync16(uint32_t dst, const void* src) {
    asm volatile("cp.async.cg.shared.global [%0], [%1], 16;" :: "r"(dst), "l"(src));
}
__device__ __forceinline__ void ldsm4(uint32_t (&r)[4], uint32_t addr) {
    asm volatile("ldmatrix.sync.aligned.m8n8.x4.shared.b16 {%0,%1,%2,%3}, [%4];"
                 : "=r"(r[0]), "=r"(r[1]), "=r"(r[2]), "=r"(r[3]) : "r"(addr));
}
__device__ __forceinline__ void mma_bf(float (&d)[4], const uint32_t (&a)[4], const uint32_t* b) {
    asm volatile("mma.sync.aligned.m16n8k16.row.col.f32.bf16.bf16.f32 "
                 "{%0,%1,%2,%3},{%4,%5,%6,%7},{%8,%9},{%0,%1,%2,%3};"
                 : "+f"(d[0]), "+f"(d[1]), "+f"(d[2]), "+f"(d[3])
                 : "r"(a[0]), "r"(a[1]), "r"(a[2]), "r"(a[3]), "r"(b[0]), "r"(b[1]));
}
__device__ __forceinline__ void mma_fp(float (&d)[4], const uint32_t (&a)[4], const uint32_t* b) {
    asm volatile("mma.sync.aligned.m16n8k16.row.col.f32.f16.f16.f32 "
                 "{%0,%1,%2,%3},{%4,%5,%6,%7},{%8,%9},{%0,%1,%2,%3};"
                 : "+f"(d[0]), "+f"(d[1]), "+f"(d[2]), "+f"(d[3])
                 : "r"(a[0]), "r"(a[1]), "r"(a[2]), "r"(a[3]), "r"(b[0]), "r"(b[1]));
}
__device__ __forceinline__ void mma_hh(uint32_t (&d)[2], const uint32_t (&a)[4], const uint32_t* b) {
    asm volatile("mma.sync.aligned.m16n8k16.row.col.f16.f16.f16.f16 "
                 "{%0,%1},{%2,%3,%4,%5},{%6,%7},{%0,%1};"
                 : "+r"(d[0]), "+r"(d[1])
                 : "r"(a[0]), "r"(a[1]), "r"(a[2]), "r"(a[3]), "r"(b[0]), "r"(b[1]));
}

// ---------------- launch 1: fused prep ----------------
#define P0 16384                 // x1 split -> bf16 pair
#define P1 (P0 + 16384)          // w_up transpose + bf16 split
#define P2 (P1 + 1024)           // lora_b up
#define P3 (P2 + 128)            // zero g_zero
#define P4 (P3 + 16384)          // w_down transpose + f16 split
#define P5 (P4 + 256)            // lora_b down
#define P6 (P5 + 128)            // zero g_tup
#define PREP_GRID (P6 + 128)     // zero g_tdn
__global__ __launch_bounds__(256) void prep_fused(
    const float* __restrict__ x1, const float* __restrict__ w_up,
    const float* __restrict__ w_up_lb,
    const float* __restrict__ w_down, const float* __restrict__ w_down_lb)
{
    __shared__ float t[32][33];
    const int bid = blockIdx.x, tid = threadIdx.x;
    if (bid < P0) {
        size_t i = (size_t)bid * 256 + tid;
        float4 v = *(const float4*)(x1 + i * 4);
        __nv_bfloat16 h0, h1, h2, h3, l0, l1, l2, l3;
        split1(v.x, h0, l0); split1(v.y, h1, l1);
        split1(v.z, h2, l2); split1(v.w, h3, l3);
        ((uint2*)g_x1h)[i] = make_uint2(packbf(h0, h1), packbf(h2, h3));
        ((uint2*)g_x1l)[i] = make_uint2(packbf(l0, l1), packbf(l2, l3));
    } else if (bid < P1) {
        int tb = bid - P0;
        int bx = tb & 255, by = tb >> 8;
        const int tx = tid & 31, ty = tid >> 5;
        const int r0 = by * 32, c0 = bx * 32;
#pragma unroll
        for (int i = 0; i < 4; i++) {
            int r = ty + i * 8;
            t[r][tx] = w_up[(size_t)(r0 + r) * INTER + c0 + tx];
        }
        __syncthreads();
#pragma unroll
        for (int i = 0; i < 4; i++) {
            int c = ty + i * 8;
            __nv_bfloat16 h, l;
            split1(t[tx][c], h, l);
            g_wupT_h[(size_t)(c0 + c) * HID + r0 + tx] = h;
            g_wupT_l[(size_t)(c0 + c) * HID + r0 + tx] = l;
        }
    } else if (bid < P2) {
        int i = (bid - P1) * 256 + tid;
        int n = i >> 5, j = i & 31;
        float v = (j < 16) ? w_up_lb[(size_t)j * INTER + n] : 0.0f;
        __nv_bfloat16 h, l;
        split1(v, h, l);
        g_lubh[i] = h; g_lubl[i] = l;
    } else if (bid < P3) {
        int i = (bid - P2) * 256 + tid;
        if (i < NB * INTER) g_zero[i] = 0;
    } else if (bid < P4) {
        int tb = bid - P3;
        int bx = tb & 63, by = tb >> 6;
        const int tx = tid & 31, ty = tid >> 5;
        const int r0 = by * 32, c0 = bx * 32;
#pragma unroll
        for (int i = 0; i < 4; i++) {
            int r = ty + i * 8;
            t[r][tx] = w_down[(size_t)(r0 + r) * HID + c0 + tx];
        }
        __syncthreads();
#pragma unroll
        for (int i = 0; i < 4; i++) {
            int c = ty + i * 8;
            __half h, ls;
            split1f(t[tx][c], h, ls);
            g_wdnT_f[(size_t)(c0 + c) * INTER + r0 + tx] = h;
            g_wdnT_ls[(size_t)(c0 + c) * INTER + r0 + tx] = ls;
        }
    } else if (bid < P5) {
        int i = (bid - P4) * 256 + tid;
        int n = i >> 5, j = i & 31;
        float v = (j < 16) ? w_down_lb[(size_t)j * HID + n] : 0.0f;
        __half h, ls;
        split1f(v, h, ls);
        g_ldbf[i] = h; g_ldbls[i] = ls;
    } else if (bid < P6) {
        int i = (bid - P5) * 256 + tid;
        ((float4*)g_tup)[i] = make_float4(0.f, 0.f, 0.f, 0.f);
    } else {
        int i = (bid - P6) * 256 + tid;
        ((float4*)g_tdn)[i] = make_float4(0.f, 0.f, 0.f, 0.f);
    }
}

// ---------------- rank-16 GEMM, K-split ----------------
template <typename TIN>
__global__ __launch_bounds__(256) void rank16_partial(
    const TIN* __restrict__ X, const float* __restrict__ A16,
    float* __restrict__ T, int K, int kchunk)
{
    const int wid = threadIdx.x >> 5, lane = threadIdx.x & 31;
    const int row0 = (blockIdx.x * 8 + wid) * 4;
    const int kbase = blockIdx.y * kchunk;
    float acc[4][16];
#pragma unroll
    for (int r = 0; r < 4; r++)
#pragma unroll
        for (int j = 0; j < 16; j++) acc[r][j] = 0.0f;
    for (int k0 = kbase + lane * 4; k0 < kbase + kchunk; k0 += 128) {
        float xv[4][4];
#pragma unroll
        for (int r = 0; r < 4; r++) {
            if constexpr (sizeof(TIN) == 4) {
                float4 v = *(const float4*)(X + (size_t)(row0 + r) * K + k0);
                xv[r][0] = v.x; xv[r][1] = v.y; xv[r][2] = v.z; xv[r][3] = v.w;
            } else {
                uint2 u = *(const uint2*)(X + (size_t)(row0 + r) * K + k0);
                __half2 p0 = *reinterpret_cast<__half2*>(&u.x);
                __half2 p1 = *reinterpret_cast<__half2*>(&u.y);
                float2 f0 = __half22float2(p0), f1 = __half22float2(p1);
                xv[r][0] = f0.x; xv[r][1] = f0.y; xv[r][2] = f1.x; xv[r][3] = f1.y;
            }
        }
#pragma unroll
        for (int e = 0; e < 4; e++) {
            const float* Ar = A16 + (size_t)(k0 + e) * 16;
            float av[16];
#pragma unroll
            for (int j = 0; j < 16; j += 4) {
                float4 a = *(const float4*)(Ar + j);
                av[j] = a.x; av[j + 1] = a.y; av[j + 2] = a.z; av[j + 3] = a.w;
            }
#pragma unroll
            for (int r = 0; r < 4; r++)
#pragma unroll
                for (int j = 0; j < 16; j++) acc[r][j] = fmaf(xv[r][e], av[j], acc[r][j]);
        }
    }
#pragma unroll
    for (int r = 0; r < 4; r++)
#pragma unroll
        for (int j = 0; j < 16; j++)
#pragma unroll
            for (int o = 16; o > 0; o >>= 1)
                acc[r][j] += __shfl_xor_sync(0xffffffffu, acc[r][j], o);
    if (lane < 4) {
        int r = lane;
#pragma unroll
        for (int j = 0; j < 16; j++)
            atomicAdd(&T[(size_t)(row0 + r) * 16 + j], acc[r][j]);
    }
}

template <bool F16OUT>
__global__ void lora_finalize(const float* __restrict__ T) {
    int i = blockIdx.x * blockDim.x + threadIdx.x;
    if (i >= MTOT * 32) return;
    int j = i & 31;
    float v = (j < 16) ? T[(i >> 5) * 16 + j] : 0.0f;
    if (F16OUT) {
        g_ltf[i] = __float2half(v);
    } else {
        __nv_bfloat16 h, l;
        split1(v, h, l);
        g_lth[i] = h; g_ltl[i] = l;
    }
}

// ---------------- up GEMM: bf16 3-term, swizzled, 3-stage, 1 sync/chunk -----
__global__ __launch_bounds__(256, 2) void mma_gemm_up(
    const __nv_bfloat16* __restrict__ A0, const __nv_bfloat16* __restrict__ A1,
    const __nv_bfloat16* __restrict__ B0, const __nv_bfloat16* __restrict__ B1,
    const __nv_bfloat16* __restrict__ lt0, const __nv_bfloat16* __restrict__ lt1,
    const __nv_bfloat16* __restrict__ lb0, const __nv_bfloat16* __restrict__ lb1,
    int N, int K)
{
    extern __shared__ char smem[];
    const uint32_t sbase = smem_u32(smem);
    const int tid = threadIdx.x, lane = tid & 31, wid = tid >> 5;
    const int wm = wid >> 2, wn = wid & 3;
    const int bm = blockIdx.y * BM, bn = blockIdx.x * BN;
    const int nmain = K / BK, ntot = nmain + 1;

    auto issue = [&](int c) {
        const __nv_bfloat16 *pa0, *pa1, *pb0, *pb1;
        int sa, sb;
        if (c < nmain) {
            size_t ao = (size_t)bm * K + c * BK, bo = (size_t)bn * K + c * BK;
            pa0 = A0 + ao; pa1 = A1 + ao; sa = K;
            pb0 = B0 + bo; pb1 = B1 + bo; sb = K;
        } else {
            pa0 = lt0 + (size_t)bm * 32; pa1 = lt1 + (size_t)bm * 32; sa = 32;
            pb0 = lb0 + (size_t)bn * 32; pb1 = lb1 + (size_t)bn * 32; sb = 32;
        }
        uint32_t stage = sbase + (c % 3) * UP_STAGE_B;
#pragma unroll
        for (int q = 0; q < 8; q++) {
            int qi = tid + q * 256;                  // 0..2047
            int arr = qi >> 9, idx = qi & 511;
            int r = idx >> 2, cc = idx & 3;
            const __nv_bfloat16* src;
            if (arr == 0)      src = pa0 + (size_t)r * sa + cc * 8;
            else if (arr == 1) src = pa1 + (size_t)r * sa + cc * 8;
            else if (arr == 2) src = pb0 + (size_t)r * sb + cc * 8;
            else               src = pb1 + (size_t)r * sb + cc * 8;
            cpasync16(stage + arr * UP_TILE + sw64((uint32_t)(r * 64 + cc * 16)), src);
        }
        asm volatile("cp.async.commit_group;");
    };

    issue(0);
    issue(1);

    float acc[4][4][4];
#pragma unroll
    for (int mf = 0; mf < 4; mf++)
#pragma unroll
        for (int nf = 0; nf < 4; nf++)
#pragma unroll
            for (int q = 0; q < 4; q++) acc[mf][nf][q] = 0.0f;

    for (int c = 0; c < ntot; c++) {
        if (c + 1 < ntot) {
            asm volatile("cp.async.wait_group 1;" ::: "memory");
        } else {
            asm volatile("cp.async.wait_group 0;" ::: "memory");
        }
        __syncthreads();
        if (c + 2 < ntot) issue(c + 2);
        const uint32_t stage = sbase + (c % 3) * UP_STAGE_B;
#pragma unroll
        for (int s = 0; s < 2; s++) {
            uint32_t ah[4][4], al[4][4], bh[4][2], bl[4][2];
#pragma unroll
            for (int mf = 0; mf < 4; mf++) {
                int row = wm * 64 + mf * 16 + (lane & 15);
                int cc = s * 2 + (lane >> 4);
                uint32_t off = sw64((uint32_t)(row * 64 + cc * 16));
                ldsm4(ah[mf], stage + off);
                ldsm4(al[mf], stage + UP_TILE + off);
            }
#pragma unroll
            for (int nf16 = 0; nf16 < 2; nf16++) {
                int row = wn * 32 + nf16 * 16 + (lane & 7) + (((lane >> 4) & 1) << 3);
                int cc = s * 2 + ((lane >> 3) & 1);
                uint32_t off = sw64((uint32_t)(row * 64 + cc * 16));
                uint32_t t[4];
                ldsm4(t, stage + 2 * UP_TILE + off);
                bh[nf16 * 2][0] = t[0]; bh[nf16 * 2][1] = t[1];
                bh[nf16 * 2 + 1][0] = t[2]; bh[nf16 * 2 + 1][1] = t[3];
                ldsm4(t, stage + 3 * UP_TILE + off);
                bl[nf16 * 2][0] = t[0]; bl[nf16 * 2][1] = t[1];
                bl[nf16 * 2 + 1][0] = t[2]; bl[nf16 * 2 + 1][1] = t[3];
            }
#pragma unroll
            for (int mf = 0; mf < 4; mf++)
#pragma unroll
                for (int nf = 0; nf < 4; nf++) {
                    mma_bf(acc[mf][nf], ah[mf], bh[nf]);
                    mma_bf(acc[mf][nf], al[mf], bh[nf]);
                    mma_bf(acc[mf][nf], ah[mf], bl[nf]);
                }
        }
    }

    // epilogue: relu + zero counts + fp16 x2 store
    const int r0 = lane >> 2, c0 = (lane & 3) * 2;
    __shared__ int zc[BN];
    __syncthreads();
    if (tid < BN) zc[tid] = 0;
    __syncthreads();
    int cnt0[4] = {0, 0, 0, 0}, cnt1[4] = {0, 0, 0, 0};
#pragma unroll
    for (int mf = 0; mf < 4; mf++)
#pragma unroll
        for (int nf = 0; nf < 4; nf++) {
            float v0 = fmaxf(acc[mf][nf][0], 0.0f);
            float v1 = fmaxf(acc[mf][nf][1], 0.0f);
            float v2 = fmaxf(acc[mf][nf][2], 0.0f);
            float v3 = fmaxf(acc[mf][nf][3], 0.0f);
            cnt0[nf] += (v0 == 0.0f) + (v2 == 0.0f);
            cnt1[nf] += (v1 == 0.0f) + (v3 == 0.0f);
            int ra = bm + wm * 64 + mf * 16 + r0;
            int col = bn + wn * 32 + nf * 8 + c0;
            size_t pa = (size_t)ra * (N / 2) + (col >> 1);
            size_t pb = (size_t)(ra + 8) * (N / 2) + (col >> 1);
            ((uint32_t*)g_x2f)[pa] = packh(__float2half(v0), __float2half(v1));
            ((uint32_t*)g_x2f)[pb] = packh(__float2half(v2), __float2half(v3));
        }
#pragma unroll
    for (int nf = 0; nf < 4; nf++) {
        atomicAdd(&zc[wn * 32 + nf * 8 + c0], cnt0[nf]);
        atomicAdd(&zc[wn * 32 + nf * 8 + c0 + 1], cnt1[nf]);
    }
    __syncthreads();
    if (tid < BN) {
        int b = bm / SEQ;
        atomicAdd(&g_zero[b * INTER + bn + tid], zc[tid]);
    }
}

// ---------------- down GEMM (round-11): fp16 dual-acc, 128x128, 3-stage -----
__global__ __launch_bounds__(256, 2) void mma_gemm_down(
    const __half* __restrict__ A0,
    const __half* __restrict__ B0, const __half* __restrict__ B1,
    const __half* __restrict__ lt0,
    const __half* __restrict__ lb0, const __half* __restrict__ lb1,
    float* __restrict__ C, int N, int K)
{
    extern __shared__ char smem[];
    const uint32_t sbase = smem_u32(smem);
    const int tid = threadIdx.x, lane = tid & 31, wid = tid >> 5;
    const int wm = wid >> 2, wn = wid & 3;
    const int bm = blockIdx.y * BM, bn = blockIdx.x * BN;
    const int nmain = K / BK, ntot = nmain + 1;

    auto issue = [&](int c) {
        const __half *pa, *pb0, *pb1;
        int sa, sb;
        if (c < nmain) {
            pa = A0 + (size_t)bm * K + c * BK; sa = K;
            pb0 = B0 + (size_t)bn * K + c * BK;
            pb1 = B1 + (size_t)bn * K + c * BK; sb = K;
        } else {
            pa = lt0 + (size_t)bm * 32; sa = 32;
            pb0 = lb0 + (size_t)bn * 32; pb1 = lb1 + (size_t)bn * 32; sb = 32;
        }
        uint32_t stage = sbase + (c % 3) * DN_STAGE_B;
#pragma unroll
        for (int q = 0; q < 6; q++) {
            int qi = tid + q * 256;                  // 0..1535
            int arr = qi >> 9, idx = qi & 511;
            int r = idx >> 2, cc = idx & 3;
            const __half* src;
            if (arr == 0)      src = pa + (size_t)r * sa + cc * 8;
            else if (arr == 1) src = pb0 + (size_t)r * sb + cc * 8;
            else               src = pb1 + (size_t)r * sb + cc * 8;
            cpasync16(stage + arr * TILE_B + r * (LDSTRIDE * 2) + cc * 16, src);
        }
        asm volatile("cp.async.commit_group;");
    };

    issue(0);
    issue(1);

    float acc1[4][4][4];
    uint32_t acc2[4][4][2];
#pragma unroll
    for (int mf = 0; mf < 4; mf++)
#pragma unroll
        for (int nf = 0; nf < 4; nf++) {
#pragma unroll
            for (int q = 0; q < 4; q++) acc1[mf][nf][q] = 0.0f;
            acc2[mf][nf][0] = 0u; acc2[mf][nf][1] = 0u;
        }

    for (int c = 0; c < ntot; c++) {
        if (c + 1 < ntot) {
            asm volatile("cp.async.wait_group 1;" ::: "memory");
        } else {
            asm volatile("cp.async.wait_group 0;" ::: "memory");
        }
        __syncthreads();
        if (c + 2 < ntot) issue(c + 2);
        const uint32_t stage = sbase + (c % 3) * DN_STAGE_B;
#pragma unroll
        for (int s = 0; s < 2; s++) {
            uint32_t ah[4][4], bh[4][2], bl[4][2];
#pragma unroll
            for (int mf = 0; mf < 4; mf++) {
                uint32_t ra = stage +
                    ((wm * 64 + mf * 16 + (lane & 15)) * LDSTRIDE +
                     s * 16 + (lane >> 4) * 8) * 2;
                ldsm4(ah[mf], ra);
            }
#pragma unroll
            for (int nf16 = 0; nf16 < 2; nf16++) {
                uint32_t rb = stage + TILE_B +
                    ((wn * 32 + nf16 * 16 + (lane & 7) + (((lane >> 4) & 1) << 3)) * LDSTRIDE +
                     s * 16 + ((lane >> 3) & 1) * 8) * 2;
                uint32_t t[4];
                ldsm4(t, rb);
                bh[nf16 * 2][0] = t[0]; bh[nf16 * 2][1] = t[1];
                bh[nf16 * 2 + 1][0] = t[2]; bh[nf16 * 2 + 1][1] = t[3];
                ldsm4(t, rb + TILE_B);
                bl[nf16 * 2][0] = t[0]; bl[nf16 * 2][1] = t[1];
                bl[nf16 * 2 + 1][0] = t[2]; bl[nf16 * 2 + 1][1] = t[3];
            }
#pragma unroll
            for (int mf = 0; mf < 4; mf++)
#pragma unroll
                for (int nf = 0; nf < 4; nf++) {
                    mma_fp(acc1[mf][nf], ah[mf], bh[nf]);
                    mma_hh(acc2[mf][nf], ah[mf], bl[nf]);
                }
        }
    }

    const int r0 = lane >> 2, c0 = (lane & 3) * 2;
    const float sc = 0.0009765625f;   // 2^-10
#pragma unroll
    for (int mf = 0; mf < 4; mf++)
#pragma unroll
        for (int nf = 0; nf < 4; nf++) {
            float2 f0 = __half22float2(*reinterpret_cast<__half2*>(&acc2[mf][nf][0]));
            float2 f1 = __half22float2(*reinterpret_cast<__half2*>(&acc2[mf][nf][1]));
            int ra = bm + wm * 64 + mf * 16 + r0;
            int col = bn + wn * 32 + nf * 8 + c0;
            *(float2*)&C[(size_t)ra * N + col] =
                make_float2(acc1[mf][nf][0] + sc * f0.x, acc1[mf][nf][1] + sc * f0.y);
            *(float2*)&C[(size_t)(ra + 8) * N + col] =
                make_float2(acc1[mf][nf][2] + sc * f1.x, acc1[mf][nf][3] + sc * f1.y);
        }
}

// ---------------- topk + gather ----------------
__global__ void topk_kernel() {
    const int b = blockIdx.x, tid = threadIdx.x;
    __shared__ unsigned red[256];
    __shared__ int chosen[KSEL];
    for (int sel = 0; sel < KSEL; sel++) {
        unsigned best = 0xFFFFFFFFu;
        for (int j = tid; j < INTER; j += 256) {
            bool skip = false;
            for (int c = 0; c < sel; c++) if (chosen[c] == j) skip = true;
            if (!skip) best = min(best, ((unsigned)g_zero[b * INTER + j] << 13) | (unsigned)j);
        }
        red[tid] = best;
        __syncthreads();
        for (int s = 128; s > 0; s >>= 1) {
            if (tid < s) red[tid] = min(red[tid], red[tid + s]);
            __syncthreads();
        }
        if (tid == 0) { chosen[sel] = (int)(red[0] & 8191u); g_topk[b * KSEL + sel] = chosen[sel]; }
        __syncthreads();
    }
}

__global__ void gather_kernel(float* __restrict__ out) {
    int idx = blockIdx.x * blockDim.x + threadIdx.x;
    if (idx >= NB * SEQ * KSEL) return;
    int i = idx % KSEL, row = idx / KSEL, b = row / SEQ;
    out[idx] = __half2float(g_x2f[(size_t)row * INTER + g_topk[b * KSEL + i]]);
}

// ---------------- launch ----------------
extern "C" void kernel_launch(void* const* d_in, const int* in_sizes, int n_in,
                              void* d_out, int out_size)
{
    const float* x1 = (const float*)d_in[0];
    const float* w_up = (const float*)d_in[1];
    const float* w_up_la = (const float*)d_in[2];
    const float* w_up_lb = (const float*)d_in[3];
    const float* w_down = (const float*)d_in[4];
    const float* w_down_la = (const float*)d_in[5];
    const float* w_down_lb = (const float*)d_in[6];
    float* out = (float*)d_out;

    float *ptup, *ptdn;
    __nv_bfloat16 *x1h, *x1l, *uh, *ul, *lth, *ltl, *ubh, *ubl;
    __half *x2f, *wdf, *wdls, *ltf, *dbf, *dbls;
    cudaGetSymbolAddress((void**)&ptup, g_tup);
    cudaGetSymbolAddress((void**)&ptdn, g_tdn);
    cudaGetSymbolAddress((void**)&x1h, g_x1h);
    cudaGetSymbolAddress((void**)&x1l, g_x1l);
    cudaGetSymbolAddress((void**)&uh, g_wupT_h);
    cudaGetSymbolAddress((void**)&ul, g_wupT_l);
    cudaGetSymbolAddress((void**)&lth, g_lth);
    cudaGetSymbolAddress((void**)&ltl, g_ltl);
    cudaGetSymbolAddress((void**)&ubh, g_lubh);
    cudaGetSymbolAddress((void**)&ubl, g_lubl);
    cudaGetSymbolAddress((void**)&x2f, g_x2f);
    cudaGetSymbolAddress((void**)&wdf, g_wdnT_f);
    cudaGetSymbolAddress((void**)&wdls, g_wdnT_ls);
    cudaGetSymbolAddress((void**)&ltf, g_ltf);
    cudaGetSymbolAddress((void**)&dbf, g_ldbf);
    cudaGetSymbolAddress((void**)&dbls, g_ldbls);

    cudaFuncSetAttribute((const void*)mma_gemm_up,
                         cudaFuncAttributeMaxDynamicSharedMemorySize, UP_SMEM);
    cudaFuncSetAttribute((const void*)mma_gemm_down,
                         cudaFuncAttributeMaxDynamicSharedMemorySize, DN_SMEM);

    // 1: all elementwise prep
    prep_fused<<<PREP_GRID, 256>>>(x1, w_up, w_up_lb, w_down, w_down_lb);
    // 2: t_up = x1 @ w_up_lora_a  (fp32, exact — counts depend on it)
    rank16_partial<float><<<dim3(MTOT / 32, 4), 256>>>(x1, w_up_la, ptup, HID, HID / 4);
    // 3: finalize lora-T up (bf16 pair)
    lora_finalize<false><<<(MTOT * 32 + 255) / 256, 256>>>(ptup);
    // 4: up GEMM (bf16 3-term, swizzled 3-stage)  [profiled slot]
    mma_gemm_up<<<dim3(INTER / BN, MTOT / BM), 256, UP_SMEM>>>(
        x1h, x1l, uh, ul, lth, ltl, ubh, ubl, INTER, HID);
    // 5: t_down = x2f @ w_down_lora_a
    rank16_partial<__half><<<dim3(MTOT / 32, 8), 256>>>(x2f, w_down_la, ptdn, INTER, INTER / 8);
    // 6: finalize lora-T down (fp16)
    lora_finalize<true><<<(MTOT * 32 + 255) / 256, 256>>>(ptdn);
    // 7: down GEMM (round-11 config)
    mma_gemm_down<<<dim3(HID / BN, MTOT / BM), 256, DN_SMEM>>>(
        x2f, wdf, wdls, ltf, dbf, dbls, out, HID, INTER);
    // 8/9: topk + gather
    topk_kernel<<<NB, 256>>>();
    gather_kernel<<<(NB * SEQ * KSEL + 255) / 256, 256>>>(out + (size_t)MTOT * HID);
}